// round 1
// baseline (speedup 1.0000x reference)
#include <cuda_runtime.h>
#include <cstdint>

#define IN_DIM   5000
#define TOPK     50
#define BATCH    16384
#define H1       32
#define H2       16
#define OUT_DIM  30

#define NCHUNK   16
#define CHUNK    313   // 16*313 = 5008 >= 5000

// scratch (no allocations allowed in kernel_launch)
__device__ int g_part[NCHUNK][IN_DIM + 16];
__device__ int g_topk_idx[64];

static __device__ __forceinline__ unsigned long long key64(float f, int j) {
    unsigned int u = __float_as_uint(f);
    u = (u & 0x80000000u) ? ~u : (u | 0x80000000u);   // monotonic: larger float -> larger key
    return (((unsigned long long)u) << 13) | (unsigned long long)(8191 - j); // tie: lower j wins
}

// ---------------------------------------------------------------------------
// Kernel 1: partial descending-rank counts per j-chunk
// grid = (40, NCHUNK), block = 128
// ---------------------------------------------------------------------------
__global__ void k_rank(const float* __restrict__ logits) {
    __shared__ unsigned long long skey[CHUNK];
    const int c  = blockIdx.y;
    const int j0 = c * CHUNK;

    for (int t = threadIdx.x; t < CHUNK; t += blockDim.x) {
        int j = j0 + t;
        unsigned long long kj = 0ull;            // 0 < any valid key (low 13 bits >= 3192)
        if (j < IN_DIM) kj = key64(logits[j], j);
        skey[t] = kj;
    }
    __syncthreads();

    const int i = blockIdx.x * blockDim.x + threadIdx.x;
    if (i >= IN_DIM) return;
    const unsigned long long ki = key64(logits[i], i);

    int cnt = 0;
#pragma unroll 8
    for (int t = 0; t < CHUNK; t++)
        cnt += (skey[t] > ki) ? 1 : 0;

    g_part[c][i] = cnt;
}

// ---------------------------------------------------------------------------
// Kernel 2: finalize ranks -> mask + compact index list (slot = rank, no atomics)
// grid = 20, block = 256
// ---------------------------------------------------------------------------
__global__ void k_final(float* __restrict__ mask_out) {
    const int i = blockIdx.x * blockDim.x + threadIdx.x;
    if (i >= IN_DIM) return;
    int rank = 0;
#pragma unroll
    for (int c = 0; c < NCHUNK; c++)
        rank += g_part[c][i];
    const bool sel = (rank < TOPK);
    if (mask_out) mask_out[i] = sel ? 1.0f : 0.0f;
    if (sel) g_topk_idx[rank] = i;
}

// ---------------------------------------------------------------------------
// Kernel 3: fused gather + 3-layer MLP, one thread per batch row
// grid = 128, block = 128
// ---------------------------------------------------------------------------
__global__ void __launch_bounds__(128, 1)
k_mlp(const float* __restrict__ x,
      const float* __restrict__ W1, const float* __restrict__ b1,
      const float* __restrict__ W2, const float* __restrict__ b2,
      const float* __restrict__ W3, const float* __restrict__ b3,
      float* __restrict__ out) {
    __shared__ int   sidx[TOPK];
    __shared__ float sW1[TOPK][H1];     // gathered rows of W1
    __shared__ float sW2[H1][H2];
    __shared__ float sW3[H2][OUT_DIM];
    __shared__ float sb1[H1], sb2[H2], sb3[OUT_DIM];

    const int tid = threadIdx.x;
    if (tid < TOPK) sidx[tid] = g_topk_idx[tid];
    if (tid < H1)      sb1[tid] = b1[tid];
    if (tid < H2)      sb2[tid] = b2[tid];
    if (tid < OUT_DIM) sb3[tid] = b3[tid];
    __syncthreads();   // sidx ready before W1 gather

    for (int t = tid; t < TOPK * H1; t += blockDim.x) {
        int k = t >> 5, j = t & 31;
        sW1[k][j] = W1[(long)sidx[k] * H1 + j];
    }
    for (int t = tid; t < H1 * H2; t += blockDim.x)
        sW2[t / H2][t % H2] = W2[t];
    for (int t = tid; t < H2 * OUT_DIM; t += blockDim.x)
        sW3[t / OUT_DIM][t % OUT_DIM] = W3[t];
    __syncthreads();

    const int row = blockIdx.x * blockDim.x + tid;
    if (row >= BATCH) return;
    const float* __restrict__ xr = x + (long)row * IN_DIM;

    // gather all 50 inputs first: MLP = 50, hides DRAM latency at low occupancy
    float xv[TOPK];
#pragma unroll
    for (int k = 0; k < TOPK; k++)
        xv[k] = __ldg(xr + sidx[k]);

    float a1[H1];
#pragma unroll
    for (int j = 0; j < H1; j++) a1[j] = sb1[j];
#pragma unroll
    for (int k = 0; k < TOPK; k++) {
        const float v = xv[k];
#pragma unroll
        for (int j = 0; j < H1; j++)
            a1[j] = fmaf(v, sW1[k][j], a1[j]);
    }
#pragma unroll
    for (int j = 0; j < H1; j++) a1[j] = fmaxf(a1[j], 0.0f);

    float a2[H2];
#pragma unroll
    for (int j = 0; j < H2; j++) a2[j] = sb2[j];
#pragma unroll
    for (int i = 0; i < H1; i++) {
        const float v = a1[i];
#pragma unroll
        for (int j = 0; j < H2; j++)
            a2[j] = fmaf(v, sW2[i][j], a2[j]);
    }
#pragma unroll
    for (int j = 0; j < H2; j++) a2[j] = fmaxf(a2[j], 0.0f);

    float* __restrict__ orow = out + (long)row * OUT_DIM;
#pragma unroll
    for (int j = 0; j < OUT_DIM; j++) {
        float s = sb3[j];
#pragma unroll
        for (int i = 0; i < H2; i++)
            s = fmaf(a2[i], sW3[i][j], s);
        orow[j] = s;
    }
}

// ---------------------------------------------------------------------------
extern "C" void kernel_launch(void* const* d_in, const int* in_sizes, int n_in,
                              void* d_out, int out_size) {
    const float* x      = (const float*)d_in[0];
    const float* logits = (const float*)d_in[1];
    const float* W1     = (const float*)d_in[2];
    const float* b1     = (const float*)d_in[3];
    const float* W2     = (const float*)d_in[4];
    const float* b2     = (const float*)d_in[5];
    const float* W3     = (const float*)d_in[6];
    const float* b3     = (const float*)d_in[7];
    // d_in[8], d_in[9]: epoch / total_epochs — unused on eval path

    float* out  = (float*)d_out;
    float* mask = nullptr;
    if (out_size >= BATCH * OUT_DIM + IN_DIM)
        mask = out + (long)BATCH * OUT_DIM;   // tuple order: (out, mask)

    k_rank <<<dim3(40, NCHUNK), 128>>>(logits);
    k_final<<<20, 256>>>(mask);
    k_mlp  <<<128, 128>>>(x, W1, b1, W2, b2, W3, b3, out);
}